// round 12
// baseline (speedup 1.0000x reference)
#include <cuda_runtime.h>
#include <cstdint>

#define D     32768          // row length
#define NT    256            // threads per CTA
#define NW    8              // warps per CTA
#define NF8   16             // 32B (v8) accesses per thread (256*16*8 = 32768)
#define NF4   32             // float4 accesses per thread (fallback path)
#define TOPK  32u
#define CAP   1024u          // candidate capacity (Gaussian mean ~200)
#define THR   2.5f           // gather threshold: E[count(x>=2.5)] ~ 200 >> 32 per row
#define NSM   148            // B200 SMs
#define OCC   8              // CTAs per SM

struct Smem {
    unsigned       ckey[CAP];          // 4 KB
    unsigned short cidx[CAP];          // 2 KB
    unsigned       hist[256];          // 1 KB
    unsigned       nc;
    unsigned       sh_b, sh_kk, sh_ce;
    unsigned       sh_red[NW + 1];
};

// ---- sm_100a 256-bit global accesses ----
__device__ __forceinline__ void ldg256_cs(const float* p, float* v) {
    asm volatile("ld.global.cs.v8.f32 {%0,%1,%2,%3,%4,%5,%6,%7}, [%8];"
                 : "=f"(v[0]), "=f"(v[1]), "=f"(v[2]), "=f"(v[3]),
                   "=f"(v[4]), "=f"(v[5]), "=f"(v[6]), "=f"(v[7])
                 : "l"(p));
}
__device__ __forceinline__ void stg256_zero(float* p) {
    asm volatile("st.global.cs.v8.f32 [%0], {%1,%1,%1,%1,%1,%1,%1,%1};"
                 :: "l"(p), "f"(0.0f) : "memory");
}

// order-preserving float -> uint key (larger float => larger key); bijective
__device__ __forceinline__ unsigned f2k(float f) {
    unsigned u = __float_as_uint(f);
    return u ^ (((unsigned)((int)u >> 31)) | 0x80000000u);
}
// exact inverse of f2k
__device__ __forceinline__ float k2f(unsigned k) {
    return (k & 0x80000000u) ? __uint_as_float(k & 0x7FFFFFFFu)
                             : __uint_as_float(~k);
}

// warp-collective: pick byte b with suffix_count(b) >= kk > suffix_count(b+1).
__device__ __forceinline__ void select_byte(const unsigned* hist, unsigned kk,
                                            unsigned* sh_b, unsigned* sh_kk,
                                            unsigned* sh_ce, int lane) {
    int base = lane * 8;
    unsigned s = 0;
#pragma unroll
    for (int j = 0; j < 8; ++j) s += hist[base + j];
    unsigned suf = s;
#pragma unroll
    for (int off = 1; off < 32; off <<= 1) {
        unsigned t = __shfl_down_sync(0xffffffffu, suf, off);
        if (lane + off < 32) suf += t;
    }
    unsigned sufnext = __shfl_down_sync(0xffffffffu, suf, 1);
    if (lane == 31) sufnext = 0;
    if (suf >= kk && sufnext < kk) {   // exactly one lane
        unsigned acc = sufnext;
#pragma unroll
        for (int j = 7; j >= 0; --j) {
            unsigned t = hist[base + j];
            if (acc + t >= kk) {
                *sh_b  = (unsigned)(base + j);
                *sh_kk = kk - acc;
                *sh_ce = t;
                break;
            }
            acc += t;
        }
    }
}

__device__ __forceinline__ float keepv(float f, unsigned idx,
                                       unsigned K, unsigned T) {
    unsigned k = f2k(f);
    if (k > K) return f;
    return (k == K && idx <= T) ? f : 0.0f;
}

__global__ void __launch_bounds__(NT, OCC)
topk_mask_kernel(const float* __restrict__ x, float* __restrict__ out, int rows) {
    __shared__ Smem sm;

    const int tid  = threadIdx.x;
    const int lane = tid & 31;
    const int wid  = tid >> 5;

    for (int row = blockIdx.x; row < rows; row += gridDim.x) {
        const size_t rowbase = (size_t)row * D;
        const float* xrow = x + rowbase;
        float*       orow = out + rowbase;

        __syncthreads();               // protect prev iteration's warp0 smem use
        sm.hist[tid] = 0;              // NT == 256: one bin per thread
        if (tid == 0) sm.nc = 0;
        __syncthreads();

        // ---- fused pass: 256-bit read stream + 256-bit zero-store stream +
        //      rare candidate gather with inline round-0 histogram ----
#pragma unroll 4
        for (int i = 0; i < NF8; ++i) {
            const unsigned off = (unsigned)(i * NT + tid) * 8u;
            float v[8];
            ldg256_cs(xrow + off, v);
            stg256_zero(orow + off);                   // independent store stream
            float m01 = fmaxf(v[0], v[1]), m23 = fmaxf(v[2], v[3]);
            float m45 = fmaxf(v[4], v[5]), m67 = fmaxf(v[6], v[7]);
            float vmax = fmaxf(fmaxf(m01, m23), fmaxf(m45, m67));
            if (!(vmax < THR)) {                       // rare (~4.8% of lanes)
#pragma unroll
                for (int j = 0; j < 8; ++j)
                    if (!(v[j] < THR)) {
                        unsigned key = f2k(v[j]);
                        unsigned pos = atomicAdd(&sm.nc, 1u);
                        if (pos < CAP) {
                            sm.ckey[pos] = key;
                            sm.cidx[pos] = (unsigned short)(off + j);
                            atomicAdd(&sm.hist[key >> 24], 1u);   // inline round 0
                        }
                    }
            }
        }
        __syncthreads();   // orders all zero-stores before the scatter below

        const unsigned n = sm.nc;
        const bool fast = (n >= TOPK && n <= CAP);

        if (fast) {
            // ==== warp0-only: select + ties + scatter ====
            if (wid == 0) {
                unsigned kk = TOPK, prefix = 0;
                // round 0: histogram already built during the gather
                select_byte(sm.hist, kk, &sm.sh_b, &sm.sh_kk, &sm.sh_ce, lane);
                __syncwarp();
                prefix = sm.sh_b << 24;
                kk = sm.sh_kk;
                // rounds 1..3
#pragma unroll
                for (int r = 1; r < 4; ++r) {
                    const int shift = 24 - 8 * r;
                    for (int j = lane; j < 256; j += 32) sm.hist[j] = 0;
                    __syncwarp();
                    const unsigned ph = prefix >> (shift + 8);
                    for (unsigned j = lane; j < n; j += 32) {
                        unsigned k = sm.ckey[j];
                        if ((k >> (shift + 8)) == ph)
                            atomicAdd(&sm.hist[(k >> shift) & 0xFFu], 1u);
                    }
                    __syncwarp();
                    select_byte(sm.hist, kk, &sm.sh_b, &sm.sh_kk, &sm.sh_ce, lane);
                    __syncwarp();
                    prefix |= sm.sh_b << shift;
                    kk = sm.sh_kk;
                }
                const unsigned K = prefix;
                const unsigned m = kk, ce = sm.sh_ce;

                unsigned T = 0xFFFFFFFFu;
                if (m != ce) {  // ties at K: T = m-th smallest index among ==K
                    unsigned myT = 0xFFFFFFFFu;
                    for (unsigned j = lane; j < n; j += 32)
                        if (sm.ckey[j] == K) {
                            unsigned idx = sm.cidx[j];
                            unsigned rless = 0;
                            for (unsigned q = 0; q < n; ++q)
                                rless += (sm.ckey[q] == K && sm.cidx[q] < idx);
                            if (rless == m - 1) myT = idx;
                        }
#pragma unroll
                    for (int off = 16; off; off >>= 1)
                        myT = min(myT, __shfl_xor_sync(0xffffffffu, myT, off));
                    T = myT;
                }

                // scatter winners over the zeros (n<=1024 -> <=32 iters/lane)
                for (unsigned j = lane; j < n; j += 32) {
                    unsigned k = sm.ckey[j];
                    if (k > K || (k == K && sm.cidx[j] <= T))
                        orow[sm.cidx[j]] = k2f(k);
                }
            }
        } else {
            // ==== exact fallback for any input: full-width radix from global ====
            const float4* src = (const float4*)xrow;
            float4*       dst = (float4*)orow;
            unsigned kk = TOPK, prefix = 0;
#pragma unroll
            for (int r = 0; r < 4; ++r) {
                const int shift = 24 - 8 * r;
                sm.hist[tid] = 0;
                __syncthreads();
                for (int i = 0; i < NF4; ++i) {
                    float4 v = __ldcg(src + i * NT + tid);
                    float fv[4] = {v.x, v.y, v.z, v.w};
#pragma unroll
                    for (int j = 0; j < 4; ++j) {
                        unsigned k = f2k(fv[j]);
                        if (r == 0 || ((k >> shift) >> 8) == ((prefix >> shift) >> 8))
                            atomicAdd(&sm.hist[(k >> shift) & 0xFFu], 1u);
                    }
                }
                __syncthreads();
                if (wid == 0) select_byte(sm.hist, kk, &sm.sh_b, &sm.sh_kk, &sm.sh_ce, lane);
                __syncthreads();
                prefix |= sm.sh_b << shift;
                kk = sm.sh_kk;
            }
            unsigned K = prefix, T = 0xFFFFFFFFu;
            const unsigned m = kk, ce = sm.sh_ce;
            if (m != ce) {   // index-cutoff bisection over global data
                unsigned lo = 0, hi = D - 1;
                while (lo < hi) {
                    unsigned mid = (lo + hi) >> 1;
                    unsigned c = 0;
                    for (int i = 0; i < NF4; ++i) {
                        float4 v = __ldcg(src + i * NT + tid);
                        unsigned base = (unsigned)(i * NT + tid) * 4u;
                        float fv[4] = {v.x, v.y, v.z, v.w};
#pragma unroll
                        for (int j = 0; j < 4; ++j)
                            c += (f2k(fv[j]) == K && base + j <= mid);
                    }
#pragma unroll
                    for (int off = 16; off; off >>= 1)
                        c += __shfl_xor_sync(0xffffffffu, c, off);
                    if (lane == 0) sm.sh_red[wid] = c;
                    __syncthreads();
                    if (wid == 0) {
                        unsigned t2 = (lane < NW) ? sm.sh_red[lane] : 0;
#pragma unroll
                        for (int off = NW / 2; off; off >>= 1)
                            t2 += __shfl_xor_sync(0xffffffffu, t2, off);
                        if (lane == 0) sm.sh_red[NW] = t2;
                    }
                    __syncthreads();
                    c = sm.sh_red[NW];
                    if (c >= m) hi = mid; else lo = mid + 1;
                }
                T = lo;
            }
            // full masked rewrite (overwrites the zeros; correct for any input)
            for (int i = 0; i < NF4; ++i) {
                float4 v = __ldcg(src + i * NT + tid);
                unsigned base = (unsigned)(i * NT + tid) * 4u;
                float4 o;
                o.x = keepv(v.x, base + 0, K, T);
                o.y = keepv(v.y, base + 1, K, T);
                o.z = keepv(v.z, base + 2, K, T);
                o.w = keepv(v.w, base + 3, K, T);
                __stcs(dst + i * NT + tid, o);
            }
        }
    }
}

extern "C" void kernel_launch(void* const* d_in, const int* in_sizes, int n_in,
                              void* d_out, int out_size) {
    const float* x = (const float*)d_in[0];
    float* out = (float*)d_out;
    int rows = in_sizes[0] / D;
    if (rows <= 0) return;
    int grid = NSM * OCC;              // persistent: one full resident wave
    if (grid > rows) grid = rows;
    topk_mask_kernel<<<grid, NT>>>(x, out, rows);
}

// round 15
// speedup vs baseline: 1.0910x; 1.0910x over previous
#include <cuda_runtime.h>
#include <cstdint>

#define D     32768          // row length
#define NT    256            // threads per CTA
#define NW    8              // warps per CTA
#define NF8   16             // 32B (v8) accesses per thread (256*16*8 = 32768)
#define NF4   32             // float4 accesses per thread (fallback path)
#define TOPK  32u
#define CAP   1024u          // candidate capacity (Gaussian mean ~200)
#define THR   2.5f           // gather threshold: E[count(x>=2.5)] ~ 200 >> 32 per row
#define OCC   6              // CTAs/SM: ~42 regs/thread allows 3 LDG.256 in flight

struct Smem {
    unsigned       ckey[CAP];          // 4 KB
    unsigned short cidx[CAP];          // 2 KB
    unsigned       hist[256];          // 1 KB
    unsigned       nc;
    unsigned       sh_b, sh_kk, sh_ce;
    unsigned       sh_red[NW + 1];
};

// ---- sm_100a 256-bit global accesses ----
__device__ __forceinline__ void ldg256_cs(const float* p, float* v) {
    asm volatile("ld.global.cs.v8.f32 {%0,%1,%2,%3,%4,%5,%6,%7}, [%8];"
                 : "=f"(v[0]), "=f"(v[1]), "=f"(v[2]), "=f"(v[3]),
                   "=f"(v[4]), "=f"(v[5]), "=f"(v[6]), "=f"(v[7])
                 : "l"(p));
}
__device__ __forceinline__ void stg256_zero(float* p) {
    asm volatile("st.global.cs.v8.f32 [%0], {%1,%1,%1,%1,%1,%1,%1,%1};"
                 :: "l"(p), "f"(0.0f) : "memory");
}

// order-preserving float -> uint key (larger float => larger key); bijective
__device__ __forceinline__ unsigned f2k(float f) {
    unsigned u = __float_as_uint(f);
    return u ^ (((unsigned)((int)u >> 31)) | 0x80000000u);
}
// exact inverse of f2k
__device__ __forceinline__ float k2f(unsigned k) {
    return (k & 0x80000000u) ? __uint_as_float(k & 0x7FFFFFFFu)
                             : __uint_as_float(~k);
}

// warp-collective: pick byte b with suffix_count(b) >= kk > suffix_count(b+1).
__device__ __forceinline__ void select_byte(const unsigned* hist, unsigned kk,
                                            unsigned* sh_b, unsigned* sh_kk,
                                            unsigned* sh_ce, int lane) {
    int base = lane * 8;
    unsigned s = 0;
#pragma unroll
    for (int j = 0; j < 8; ++j) s += hist[base + j];
    unsigned suf = s;
#pragma unroll
    for (int off = 1; off < 32; off <<= 1) {
        unsigned t = __shfl_down_sync(0xffffffffu, suf, off);
        if (lane + off < 32) suf += t;
    }
    unsigned sufnext = __shfl_down_sync(0xffffffffu, suf, 1);
    if (lane == 31) sufnext = 0;
    if (suf >= kk && sufnext < kk) {   // exactly one lane
        unsigned acc = sufnext;
#pragma unroll
        for (int j = 7; j >= 0; --j) {
            unsigned t = hist[base + j];
            if (acc + t >= kk) {
                *sh_b  = (unsigned)(base + j);
                *sh_kk = kk - acc;
                *sh_ce = t;
                break;
            }
            acc += t;
        }
    }
}

__device__ __forceinline__ float keepv(float f, unsigned idx,
                                       unsigned K, unsigned T) {
    unsigned k = f2k(f);
    if (k > K) return f;
    return (k == K && idx <= T) ? f : 0.0f;
}

// rare-path candidate push for one 8-wide chunk
__device__ __forceinline__ void gather8(const float* v, unsigned off, Smem& sm) {
    float m01 = fmaxf(v[0], v[1]), m23 = fmaxf(v[2], v[3]);
    float m45 = fmaxf(v[4], v[5]), m67 = fmaxf(v[6], v[7]);
    float vmax = fmaxf(fmaxf(m01, m23), fmaxf(m45, m67));
    if (!(vmax < THR)) {                               // rare (~4.8% of lanes)
#pragma unroll
        for (int j = 0; j < 8; ++j)
            if (!(v[j] < THR)) {
                unsigned key = f2k(v[j]);
                unsigned pos = atomicAdd(&sm.nc, 1u);
                if (pos < CAP) {
                    sm.ckey[pos] = key;
                    sm.cidx[pos] = (unsigned short)(off + j);
                    atomicAdd(&sm.hist[key >> 24], 1u);    // inline round 0
                }
            }
    }
}

__global__ void __launch_bounds__(NT, OCC)
topk_mask_kernel(const float* __restrict__ x, float* __restrict__ out) {
    __shared__ Smem sm;

    const int tid  = threadIdx.x;
    const int lane = tid & 31;
    const int wid  = tid >> 5;

    const size_t rowbase = (size_t)blockIdx.x * D;
    const float* xrow = x + rowbase;
    float*       orow = out + rowbase;

    sm.hist[tid] = 0;                  // NT == 256: one bin per thread
    if (tid == 0) sm.nc = 0;
    __syncthreads();

    // ---- fused pass, batch-3: three loads issued before stores/gather ----
#pragma unroll
    for (int i = 0; i < 15; i += 3) {
        const unsigned off0 = (unsigned)( i      * NT + tid) * 8u;
        const unsigned off1 = (unsigned)((i + 1) * NT + tid) * 8u;
        const unsigned off2 = (unsigned)((i + 2) * NT + tid) * 8u;
        float a[8], b[8], c[8];
        ldg256_cs(xrow + off0, a);
        ldg256_cs(xrow + off1, b);
        ldg256_cs(xrow + off2, c);
        stg256_zero(orow + off0);
        stg256_zero(orow + off1);
        stg256_zero(orow + off2);
        gather8(a, off0, sm);
        gather8(b, off1, sm);
        gather8(c, off2, sm);
    }
    {   // leftover chunk 15
        const unsigned off = (unsigned)(15 * NT + tid) * 8u;
        float a[8];
        ldg256_cs(xrow + off, a);
        stg256_zero(orow + off);
        gather8(a, off, sm);
    }
    __syncthreads();   // orders all zero-stores before the scatter below

    const unsigned n = sm.nc;
    const bool fast = (n >= TOPK && n <= CAP);

    if (fast) {
        // ==== warp0-only: select + ties + scatter; warps 1..7 exit now ====
        if (wid == 0) {
            unsigned kk = TOPK, prefix = 0;
            // round 0: histogram already built during the gather
            select_byte(sm.hist, kk, &sm.sh_b, &sm.sh_kk, &sm.sh_ce, lane);
            __syncwarp();
            prefix = sm.sh_b << 24;
            kk = sm.sh_kk;
            // rounds 1..3
#pragma unroll
            for (int r = 1; r < 4; ++r) {
                const int shift = 24 - 8 * r;
                for (int j = lane; j < 256; j += 32) sm.hist[j] = 0;
                __syncwarp();
                const unsigned ph = prefix >> (shift + 8);
                for (unsigned j = lane; j < n; j += 32) {
                    unsigned k = sm.ckey[j];
                    if ((k >> (shift + 8)) == ph)
                        atomicAdd(&sm.hist[(k >> shift) & 0xFFu], 1u);
                }
                __syncwarp();
                select_byte(sm.hist, kk, &sm.sh_b, &sm.sh_kk, &sm.sh_ce, lane);
                __syncwarp();
                prefix |= sm.sh_b << shift;
                kk = sm.sh_kk;
            }
            const unsigned K = prefix;
            const unsigned m = kk, ce = sm.sh_ce;

            unsigned T = 0xFFFFFFFFu;
            if (m != ce) {  // ties at K: T = m-th smallest index among ==K
                unsigned myT = 0xFFFFFFFFu;
                for (unsigned j = lane; j < n; j += 32)
                    if (sm.ckey[j] == K) {
                        unsigned idx = sm.cidx[j];
                        unsigned rless = 0;
                        for (unsigned q = 0; q < n; ++q)
                            rless += (sm.ckey[q] == K && sm.cidx[q] < idx);
                        if (rless == m - 1) myT = idx;
                    }
#pragma unroll
                for (int off = 16; off; off >>= 1)
                    myT = min(myT, __shfl_xor_sync(0xffffffffu, myT, off));
                T = myT;
            }

            // scatter winners over the zeros (n<=1024 -> <=32 iters/lane)
            for (unsigned j = lane; j < n; j += 32) {
                unsigned k = sm.ckey[j];
                if (k > K || (k == K && sm.cidx[j] <= T))
                    orow[sm.cidx[j]] = k2f(k);
            }
        }
    } else {
        // ==== exact fallback for any input: full-width radix from global ====
        const float4* src = (const float4*)xrow;
        float4*       dst = (float4*)orow;
        unsigned kk = TOPK, prefix = 0;
#pragma unroll
        for (int r = 0; r < 4; ++r) {
            const int shift = 24 - 8 * r;
            sm.hist[tid] = 0;
            __syncthreads();
            for (int i = 0; i < NF4; ++i) {
                float4 v = __ldcg(src + i * NT + tid);
                float fv[4] = {v.x, v.y, v.z, v.w};
#pragma unroll
                for (int j = 0; j < 4; ++j) {
                    unsigned k = f2k(fv[j]);
                    if (r == 0 || ((k >> shift) >> 8) == ((prefix >> shift) >> 8))
                        atomicAdd(&sm.hist[(k >> shift) & 0xFFu], 1u);
                }
            }
            __syncthreads();
            if (wid == 0) select_byte(sm.hist, kk, &sm.sh_b, &sm.sh_kk, &sm.sh_ce, lane);
            __syncthreads();
            prefix |= sm.sh_b << shift;
            kk = sm.sh_kk;
        }
        unsigned K = prefix, T = 0xFFFFFFFFu;
        const unsigned m = kk, ce = sm.sh_ce;
        if (m != ce) {   // index-cutoff bisection over global data
            unsigned lo = 0, hi = D - 1;
            while (lo < hi) {
                unsigned mid = (lo + hi) >> 1;
                unsigned c = 0;
                for (int i = 0; i < NF4; ++i) {
                    float4 v = __ldcg(src + i * NT + tid);
                    unsigned base = (unsigned)(i * NT + tid) * 4u;
                    float fv[4] = {v.x, v.y, v.z, v.w};
#pragma unroll
                    for (int j = 0; j < 4; ++j)
                        c += (f2k(fv[j]) == K && base + j <= mid);
                }
#pragma unroll
                for (int off = 16; off; off >>= 1)
                    c += __shfl_xor_sync(0xffffffffu, c, off);
                if (lane == 0) sm.sh_red[wid] = c;
                __syncthreads();
                if (wid == 0) {
                    unsigned t2 = (lane < NW) ? sm.sh_red[lane] : 0;
#pragma unroll
                    for (int off = NW / 2; off; off >>= 1)
                        t2 += __shfl_xor_sync(0xffffffffu, t2, off);
                    if (lane == 0) sm.sh_red[NW] = t2;
                }
                __syncthreads();
                c = sm.sh_red[NW];
                if (c >= m) hi = mid; else lo = mid + 1;
            }
            T = lo;
        }
        // full masked rewrite (overwrites the zeros; correct for any input)
        for (int i = 0; i < NF4; ++i) {
            float4 v = __ldcg(src + i * NT + tid);
            unsigned base = (unsigned)(i * NT + tid) * 4u;
            float4 o;
            o.x = keepv(v.x, base + 0, K, T);
            o.y = keepv(v.y, base + 1, K, T);
            o.z = keepv(v.z, base + 2, K, T);
            o.w = keepv(v.w, base + 3, K, T);
            __stcs(dst + i * NT + tid, o);
        }
    }
}

extern "C" void kernel_launch(void* const* d_in, const int* in_sizes, int n_in,
                              void* d_out, int out_size) {
    const float* x = (const float*)d_in[0];
    float* out = (float*)d_out;
    int rows = in_sizes[0] / D;
    if (rows <= 0) return;
    topk_mask_kernel<<<rows, NT>>>(x, out);
}

// round 16
// speedup vs baseline: 1.0978x; 1.0062x over previous
#include <cuda_runtime.h>
#include <cstdint>

#define D     32768          // row length
#define NT    256            // threads per CTA
#define NW    8              // warps per CTA
#define NF8   16             // 32B (v8) accesses per thread (256*16*8 = 32768)
#define NF4   32             // float4 accesses per thread (fallback path)
#define TOPK  32u
#define CAP   1024u          // candidate capacity (Gaussian mean ~200)
#define THR   2.5f           // gather threshold: E[count(x>=2.5)] ~ 200 >> 32 per row
#define OCC   8              // proven best: 8 CTAs/SM, 32 regs/thread

struct Smem {
    unsigned       ckey[CAP];          // 4 KB
    unsigned short cidx[CAP];          // 2 KB
    unsigned       hist[256];          // 1 KB
    unsigned       nc;
    unsigned       sh_b, sh_kk, sh_ce;
    unsigned       sh_red[NW + 1];
};

// ---- sm_100a 256-bit global accesses ----
__device__ __forceinline__ void ldg256_nc_cs(const float* p, float* v) {
    asm volatile("ld.global.nc.cs.v8.f32 {%0,%1,%2,%3,%4,%5,%6,%7}, [%8];"
                 : "=f"(v[0]), "=f"(v[1]), "=f"(v[2]), "=f"(v[3]),
                   "=f"(v[4]), "=f"(v[5]), "=f"(v[6]), "=f"(v[7])
                 : "l"(p));
}
__device__ __forceinline__ void stg256_zero(float* p) {
    asm volatile("st.global.cs.v8.f32 [%0], {%1,%1,%1,%1,%1,%1,%1,%1};"
                 :: "l"(p), "f"(0.0f) : "memory");
}

// order-preserving float -> uint key (larger float => larger key); bijective
__device__ __forceinline__ unsigned f2k(float f) {
    unsigned u = __float_as_uint(f);
    return u ^ (((unsigned)((int)u >> 31)) | 0x80000000u);
}
// exact inverse of f2k
__device__ __forceinline__ float k2f(unsigned k) {
    return (k & 0x80000000u) ? __uint_as_float(k & 0x7FFFFFFFu)
                             : __uint_as_float(~k);
}

// warp-collective: pick byte b with suffix_count(b) >= kk > suffix_count(b+1).
__device__ __forceinline__ void select_byte(const unsigned* hist, unsigned kk,
                                            unsigned* sh_b, unsigned* sh_kk,
                                            unsigned* sh_ce, int lane) {
    int base = lane * 8;
    unsigned s = 0;
#pragma unroll
    for (int j = 0; j < 8; ++j) s += hist[base + j];
    unsigned suf = s;
#pragma unroll
    for (int off = 1; off < 32; off <<= 1) {
        unsigned t = __shfl_down_sync(0xffffffffu, suf, off);
        if (lane + off < 32) suf += t;
    }
    unsigned sufnext = __shfl_down_sync(0xffffffffu, suf, 1);
    if (lane == 31) sufnext = 0;
    if (suf >= kk && sufnext < kk) {   // exactly one lane
        unsigned acc = sufnext;
#pragma unroll
        for (int j = 7; j >= 0; --j) {
            unsigned t = hist[base + j];
            if (acc + t >= kk) {
                *sh_b  = (unsigned)(base + j);
                *sh_kk = kk - acc;
                *sh_ce = t;
                break;
            }
            acc += t;
        }
    }
}

__device__ __forceinline__ float keepv(float f, unsigned idx,
                                       unsigned K, unsigned T) {
    unsigned k = f2k(f);
    if (k > K) return f;
    return (k == K && idx <= T) ? f : 0.0f;
}

// rare-path candidate push for one 8-wide chunk
__device__ __forceinline__ void gather8(const float* v, unsigned off, Smem& sm) {
    float m01 = fmaxf(v[0], v[1]), m23 = fmaxf(v[2], v[3]);
    float m45 = fmaxf(v[4], v[5]), m67 = fmaxf(v[6], v[7]);
    float vmax = fmaxf(fmaxf(m01, m23), fmaxf(m45, m67));
    if (!(vmax < THR)) {                               // rare (~4.8% of lanes)
#pragma unroll
        for (int j = 0; j < 8; ++j)
            if (!(v[j] < THR)) {
                unsigned key = f2k(v[j]);
                unsigned pos = atomicAdd(&sm.nc, 1u);
                if (pos < CAP) {
                    sm.ckey[pos] = key;
                    sm.cidx[pos] = (unsigned short)(off + j);
                    atomicAdd(&sm.hist[key >> 24], 1u);    // inline round 0
                }
            }
    }
}

__global__ void __launch_bounds__(NT, OCC)
topk_mask_kernel(const float* __restrict__ x, float* __restrict__ out) {
    __shared__ Smem sm;

    const int tid  = threadIdx.x;
    const int lane = tid & 31;
    const int wid  = tid >> 5;

    const size_t rowbase = (size_t)blockIdx.x * D;
    const float* xrow = x + rowbase;
    float*       orow = out + rowbase;

    sm.hist[tid] = 0;                  // NT == 256: one bin per thread
    if (tid == 0) sm.nc = 0;
    __syncthreads();

    // ---- fused pass, batch-2: LD,LD then ST,ST per iteration ----
#pragma unroll 2
    for (int i = 0; i < NF8; i += 2) {
        const unsigned off0 = (unsigned)( i      * NT + tid) * 8u;
        const unsigned off1 = (unsigned)((i + 1) * NT + tid) * 8u;
        float a[8], b[8];
        ldg256_nc_cs(xrow + off0, a);
        ldg256_nc_cs(xrow + off1, b);
        stg256_zero(orow + off0);
        stg256_zero(orow + off1);
        gather8(a, off0, sm);
        gather8(b, off1, sm);
    }
    __syncthreads();   // orders all zero-stores before the scatter below

    const unsigned n = sm.nc;
    const bool fast = (n >= TOPK && n <= CAP);

    if (fast) {
        // ==== warp0-only: select + ties + scatter; warps 1..7 exit now ====
        if (wid == 0) {
            unsigned kk = TOPK, prefix = 0;
            // round 0: histogram already built during the gather
            select_byte(sm.hist, kk, &sm.sh_b, &sm.sh_kk, &sm.sh_ce, lane);
            __syncwarp();
            prefix = sm.sh_b << 24;
            kk = sm.sh_kk;
            // rounds 1..3
#pragma unroll
            for (int r = 1; r < 4; ++r) {
                const int shift = 24 - 8 * r;
                for (int j = lane; j < 256; j += 32) sm.hist[j] = 0;
                __syncwarp();
                const unsigned ph = prefix >> (shift + 8);
                for (unsigned j = lane; j < n; j += 32) {
                    unsigned k = sm.ckey[j];
                    if ((k >> (shift + 8)) == ph)
                        atomicAdd(&sm.hist[(k >> shift) & 0xFFu], 1u);
                }
                __syncwarp();
                select_byte(sm.hist, kk, &sm.sh_b, &sm.sh_kk, &sm.sh_ce, lane);
                __syncwarp();
                prefix |= sm.sh_b << shift;
                kk = sm.sh_kk;
            }
            const unsigned K = prefix;
            const unsigned m = kk, ce = sm.sh_ce;

            unsigned T = 0xFFFFFFFFu;
            if (m != ce) {  // ties at K: T = m-th smallest index among ==K
                unsigned myT = 0xFFFFFFFFu;
                for (unsigned j = lane; j < n; j += 32)
                    if (sm.ckey[j] == K) {
                        unsigned idx = sm.cidx[j];
                        unsigned rless = 0;
                        for (unsigned q = 0; q < n; ++q)
                            rless += (sm.ckey[q] == K && sm.cidx[q] < idx);
                        if (rless == m - 1) myT = idx;
                    }
#pragma unroll
                for (int off = 16; off; off >>= 1)
                    myT = min(myT, __shfl_xor_sync(0xffffffffu, myT, off));
                T = myT;
            }

            // scatter winners over the zeros (n<=1024 -> <=32 iters/lane)
            for (unsigned j = lane; j < n; j += 32) {
                unsigned k = sm.ckey[j];
                if (k > K || (k == K && sm.cidx[j] <= T))
                    orow[sm.cidx[j]] = k2f(k);
            }
        }
    } else {
        // ==== exact fallback for any input: full-width radix from global ====
        const float4* src = (const float4*)xrow;
        float4*       dst = (float4*)orow;
        unsigned kk = TOPK, prefix = 0;
#pragma unroll
        for (int r = 0; r < 4; ++r) {
            const int shift = 24 - 8 * r;
            sm.hist[tid] = 0;
            __syncthreads();
            for (int i = 0; i < NF4; ++i) {
                float4 v = __ldcg(src + i * NT + tid);
                float fv[4] = {v.x, v.y, v.z, v.w};
#pragma unroll
                for (int j = 0; j < 4; ++j) {
                    unsigned k = f2k(fv[j]);
                    if (r == 0 || ((k >> shift) >> 8) == ((prefix >> shift) >> 8))
                        atomicAdd(&sm.hist[(k >> shift) & 0xFFu], 1u);
                }
            }
            __syncthreads();
            if (wid == 0) select_byte(sm.hist, kk, &sm.sh_b, &sm.sh_kk, &sm.sh_ce, lane);
            __syncthreads();
            prefix |= sm.sh_b << shift;
            kk = sm.sh_kk;
        }
        unsigned K = prefix, T = 0xFFFFFFFFu;
        const unsigned m = kk, ce = sm.sh_ce;
        if (m != ce) {   // index-cutoff bisection over global data
            unsigned lo = 0, hi = D - 1;
            while (lo < hi) {
                unsigned mid = (lo + hi) >> 1;
                unsigned c = 0;
                for (int i = 0; i < NF4; ++i) {
                    float4 v = __ldcg(src + i * NT + tid);
                    unsigned base = (unsigned)(i * NT + tid) * 4u;
                    float fv[4] = {v.x, v.y, v.z, v.w};
#pragma unroll
                    for (int j = 0; j < 4; ++j)
                        c += (f2k(fv[j]) == K && base + j <= mid);
                }
#pragma unroll
                for (int off = 16; off; off >>= 1)
                    c += __shfl_xor_sync(0xffffffffu, c, off);
                if (lane == 0) sm.sh_red[wid] = c;
                __syncthreads();
                if (wid == 0) {
                    unsigned t2 = (lane < NW) ? sm.sh_red[lane] : 0;
#pragma unroll
                    for (int off = NW / 2; off; off >>= 1)
                        t2 += __shfl_xor_sync(0xffffffffu, t2, off);
                    if (lane == 0) sm.sh_red[NW] = t2;
                }
                __syncthreads();
                c = sm.sh_red[NW];
                if (c >= m) hi = mid; else lo = mid + 1;
            }
            T = lo;
        }
        // full masked rewrite (overwrites the zeros; correct for any input)
        for (int i = 0; i < NF4; ++i) {
            float4 v = __ldcg(src + i * NT + tid);
            unsigned base = (unsigned)(i * NT + tid) * 4u;
            float4 o;
            o.x = keepv(v.x, base + 0, K, T);
            o.y = keepv(v.y, base + 1, K, T);
            o.z = keepv(v.z, base + 2, K, T);
            o.w = keepv(v.w, base + 3, K, T);
            __stcs(dst + i * NT + tid, o);
        }
    }
}

extern "C" void kernel_launch(void* const* d_in, const int* in_sizes, int n_in,
                              void* d_out, int out_size) {
    const float* x = (const float*)d_in[0];
    float* out = (float*)d_out;
    int rows = in_sizes[0] / D;
    if (rows <= 0) return;
    topk_mask_kernel<<<rows, NT>>>(x, out);
}